// round 14
// baseline (speedup 1.0000x reference)
#include <cuda_runtime.h>
#include <cuda_fp16.h>

#define NN 100000
#define NE 1600000
#define DIN 16
#define DD 128

// ---------------- scratch ----------------------------------------------------
__device__ float g_bufA[(size_t)NN * DD];
__device__ float g_bufB[(size_t)NN * DD];
__device__ float g_bufC[(size_t)NN * DD];
__device__ float g_deg[NN];
__device__ float g_dis[NN];
__device__ int   g_cnt[NN];
__device__ int   g_ptr[NN + 1];
__device__ int   g_cursor[NN];
__device__ int2  g_edge[NE];
__device__ int   g_bsum[128];
__device__ int   g_is64;
__device__ __half g_Wt[3][16384];    // slot0=W_comb, 1=c2_W, 2=dec_W1 ([n][k])
__device__ float g_bcomb[128];       // enc_b2 @ c1_W

// ---------------- edge_index dtype detection ---------------------------------
__global__ void k_detect(const unsigned int* __restrict__ w) {
    int nonzero_odd = 0;
    for (int i = threadIdx.x; i < 2048; i += 32)
        if ((i & 1) && w[i] != 0u) nonzero_odd = 1;
    nonzero_odd = __any_sync(0xffffffffu, nonzero_odd);
    if (threadIdx.x == 0) g_is64 = nonzero_odd ? 0 : 1;
}

__device__ __forceinline__ int load_idx(const void* ei, long long pos, int is64) {
    if (is64) return (int)((const long long*)ei)[pos];
    return ((const int*)ei)[pos];
}

// ---------------- weight convert (c2_W -> slot1, dec_W1 -> slot2) -------------
__global__ void k_splitW(const float* __restrict__ W1m,
                         const float* __restrict__ W2m) {
    int id = blockIdx.x * blockDim.x + threadIdx.x;  // 32768
    int m = id >> 14;
    int rem = id & 16383;
    int k = rem >> 7, n = rem & 127;
    const float* Wm = (m == 0) ? W1m : W2m;
    g_Wt[m + 1][n * 128 + k] = __float2half_rn(Wm[k * 128 + n]);
}

// ---------------- composite weight: W_comb = enc_W2 @ c1_W --------------------
__global__ void k_combine(const float* __restrict__ W2e,
                          const float* __restrict__ c1W,
                          const float* __restrict__ b2e) {
    __shared__ float row[128];
    __shared__ float part[4][128];
    int k = blockIdx.x;
    int tid = threadIdx.x;           // 512
    int n = tid & 127, jg = tid >> 7;
    if (tid < 128) row[tid] = W2e[k * 128 + tid];
    __syncthreads();
    float acc = 0.f;
    #pragma unroll 8
    for (int j = jg * 32; j < jg * 32 + 32; j++)
        acc += row[j] * c1W[j * 128 + n];
    part[jg][n] = acc;
    __syncthreads();
    if (tid < 128) {
        float a = part[0][tid] + part[1][tid] + part[2][tid] + part[3][tid];
        g_Wt[0][tid * 128 + k] = __float2half_rn(a);
        if (k == 0) {
            float bacc = 0.f;
            #pragma unroll 8
            for (int j = 0; j < 128; j++) bacc += b2e[j] * c1W[j * 128 + tid];
            g_bcomb[tid] = bacc;
        }
    }
}

// ---------------- graph preprocessing ----------------------------------------
__global__ void k_zero_node(void) {
    int i = blockIdx.x * blockDim.x + threadIdx.x;
    if (i < NN) { g_deg[i] = 0.0f; g_cnt[i] = 0; }
}

__global__ void k_hist(const void* __restrict__ ei,
                       const float* __restrict__ ew) {
    int e = blockIdx.x * blockDim.x + threadIdx.x;
    int is64 = g_is64;
    if (e < NE) {
        int c = load_idx(ei, (long long)NE + e, is64);
        if ((unsigned)c >= NN) c = 0;
        atomicAdd(&g_deg[c], ew[e]);
        atomicAdd(&g_cnt[c], 1);
    }
}

__global__ void k_scan1(void) {
    __shared__ int sh[1024];
    int tid = threadIdx.x;
    int i = blockIdx.x * 1024 + tid;
    if (i < NN) g_dis[i] = rsqrtf(g_deg[i] + 1.0f);
    int v = (i < NN) ? g_cnt[i] : 0;
    sh[tid] = v;
    __syncthreads();
    #pragma unroll
    for (int off = 1; off < 1024; off <<= 1) {
        int t = (tid >= off) ? sh[tid - off] : 0;
        __syncthreads();
        sh[tid] += t;
        __syncthreads();
    }
    int incl = sh[tid];
    if (i < NN) g_ptr[i] = incl - v;
    if (tid == 1023) g_bsum[blockIdx.x] = incl;
}

__global__ void k_scan2(int nblocks) {
    __shared__ int wsum[4];
    int t = threadIdx.x;
    int lane = t & 31, wid = t >> 5;
    int v = (t < nblocks) ? g_bsum[t] : 0;
    int x = v;
    #pragma unroll
    for (int off = 1; off < 32; off <<= 1) {
        int y = __shfl_up_sync(0xffffffffu, x, off);
        if (lane >= off) x += y;
    }
    if (lane == 31) wsum[wid] = x;
    __syncthreads();
    int add = 0;
    for (int w = 0; w < wid; w++) add += wsum[w];
    x += add;
    if (t < nblocks) g_bsum[t] = x - v;
}

__global__ void k_scan3(void) {
    int i = blockIdx.x * blockDim.x + threadIdx.x;
    if (i < NN) {
        int p = g_ptr[i] + g_bsum[i >> 10];
        g_ptr[i] = p;
        g_cursor[i] = p;
    }
    if (i == 0) g_ptr[NN] = NE;
}

__global__ void k_fill(const void* __restrict__ ei,
                       const float* __restrict__ ew) {
    int e = blockIdx.x * blockDim.x + threadIdx.x;
    int is64 = g_is64;
    if (e < NE) {
        int r = load_idx(ei, e, is64);
        int c = load_idx(ei, (long long)NE + e, is64);
        if ((unsigned)r >= NN) r = 0;
        if ((unsigned)c >= NN) c = 0;
        int pos = atomicAdd(&g_cursor[c], 1);
        if ((unsigned)pos < NE) {
            float nrm = g_dis[r] * ew[e] * g_dis[c];
            g_edge[pos] = make_int2(r, __float_as_int(nrm));
        }
    }
}

// ---------------- tensor-core GEMM: [M,128] @ [128,128], single fp16 product --
#define PITCH 136
#define EXT_FLOATS 4224

__device__ __forceinline__ void mma_f16(float* c, const unsigned* a,
                                        const unsigned* b) {
    asm volatile(
        "mma.sync.aligned.m16n8k16.row.col.f32.f16.f16.f32 "
        "{%0,%1,%2,%3}, {%4,%5,%6,%7}, {%8,%9}, {%0,%1,%2,%3};\n"
        : "+f"(c[0]), "+f"(c[1]), "+f"(c[2]), "+f"(c[3])
        : "r"(a[0]), "r"(a[1]), "r"(a[2]), "r"(a[3]), "r"(b[0]), "r"(b[1]));
}

__device__ __forceinline__ void ldsm4(unsigned* r, unsigned addr) {
    asm volatile(
        "ldmatrix.sync.aligned.m8n8.x4.shared.b16 {%0,%1,%2,%3}, [%4];"
        : "=r"(r[0]), "=r"(r[1]), "=r"(r[2]), "=r"(r[3]) : "r"(addr));
}

__device__ __forceinline__ unsigned pack_f16(float v0, float v1) {
    __half2 h = __floats2half2_rn(v0, v1);
    return *(unsigned*)&h;
}

// MODE 0: plain (A fp16 rows); MODE 1: encoder-fused input; MODE 2: decoder
// OUT16: store C as fp16 (feeds aggregation / next GEMM)
template <int MODE, int OUT16>
__global__ __launch_bounds__(512, 2)
void k_gemm(const __half* __restrict__ A,
            const __half* __restrict__ Wt,
            const float* __restrict__ bias,
            float* __restrict__ C,
            int M, int relu,
            const float* __restrict__ xin,
            const float* __restrict__ W1,
            const float* __restrict__ b1,
            const float* __restrict__ W2,
            const float* __restrict__ b2)
{
    extern __shared__ __half sm[];
    __half* Ah = sm;                  // [128][PITCH]
    __half* Wh = Ah + 128 * PITCH;    // [128][PITCH] transposed [n][k]
    float* ext = (float*)(Wh + 128 * PITCH);

    int tid = threadIdx.x;
    int m0 = blockIdx.x * 128;

    // ---- stage W (raw fp16 copy) --------------------------------------------
    {
        int n = tid >> 2;
        int kq = (tid & 3) * 32;
        const uint4* src = (const uint4*)(Wt + n * 128 + kq);
        uint4* dst = (uint4*)(Wh + n * PITCH + kq);
        #pragma unroll
        for (int i = 0; i < 4; i++) dst[i] = src[i];
    }

    if (MODE == 1) {
        float* xs  = ext;
        float* w1s = ext + 2048;
        float* b1s = ext + 4096;
        {
            const float4* x4 = (const float4*)xin;
            int lim4 = M * 4;
            int g = m0 * 4 + tid;
            ((float4*)xs)[tid] =
                (g < lim4) ? x4[g] : make_float4(0.f, 0.f, 0.f, 0.f);
            ((float4*)w1s)[tid] = ((const float4*)W1)[tid];
            if (tid < 32) ((float4*)b1s)[tid] = ((const float4*)b1)[tid];
        }
        __syncthreads();
        {
            int r = tid >> 2;
            int c4 = (tid & 3) * 2;
            float xr[16];
            #pragma unroll
            for (int k = 0; k < 4; k++) {
                float4 v = ((const float4*)(xs + r * 16))[k];
                xr[4 * k] = v.x; xr[4 * k + 1] = v.y;
                xr[4 * k + 2] = v.z; xr[4 * k + 3] = v.w;
            }
            #pragma unroll 4
            for (int p = 0; p < 16; p++) {
                int n0 = c4 + 8 * p;
                float2 bb = *(const float2*)(b1s + n0);
                float a0 = bb.x, a1 = bb.y;
                #pragma unroll
                for (int k = 0; k < 16; k++) {
                    float2 wv = *(const float2*)(w1s + k * 128 + n0);
                    a0 += xr[k] * wv.x;
                    a1 += xr[k] * wv.y;
                }
                a0 = fmaxf(a0, 0.0f);
                a1 = fmaxf(a1, 0.0f);
                *(unsigned*)&Ah[r * PITCH + n0] = pack_f16(a0, a1);
            }
        }
    } else {
        // ---- stage A tile (fp16 rows, raw copy) -----------------------------
        int r = tid >> 2;
        int kq = (tid & 3) * 32;
        int grow = m0 + r;
        if (grow < M) {
            const uint4* src = (const uint4*)(A + (size_t)grow * DD + kq);
            uint4* dst = (uint4*)(Ah + r * PITCH + kq);
            #pragma unroll
            for (int i = 0; i < 4; i++) dst[i] = src[i];
        } else {
            uint4* dst = (uint4*)(Ah + r * PITCH + kq);
            uint4 z = make_uint4(0u, 0u, 0u, 0u);
            #pragma unroll
            for (int i = 0; i < 4; i++) dst[i] = z;
        }
    }

    if (MODE == 2) {
        float* w2s = ext;
        if (tid < 64) ((float4*)w2s)[tid] = ((const float4*)W2)[tid];
        if (tid < 128) { ext[256 + tid] = 0.0f; ext[384 + tid] = 0.0f; }
    }
    __syncthreads();

    int wid = tid >> 5;
    int lane = tid & 31;
    int gr = lane >> 2;
    int qc = lane & 3;
    int warp_m = (wid & 3) * 32;
    int warp_n = (wid >> 2) * 32;

    unsigned AhB = (unsigned)__cvta_generic_to_shared(Ah);
    unsigned WhB = AhB + 128 * PITCH * 2;

    int arow = (lane & 7) + ((lane >> 3) & 1) * 8;
    int acol = (lane >> 4) * 8;
    unsigned aoff[2];
    #pragma unroll
    for (int mt = 0; mt < 2; mt++)
        aoff[mt] = (unsigned)(((warp_m + mt * 16 + arow) * PITCH + acol) * 2);

    int bg = lane >> 3;
    unsigned boff[2];
    #pragma unroll
    for (int p = 0; p < 2; p++) {
        int nrow = warp_n + (2 * p + (bg >> 1)) * 8 + (lane & 7);
        int bcol = (bg & 1) * 8;
        boff[p] = (unsigned)((nrow * PITCH + bcol) * 2);
    }

    float acc[2][4][4];
    #pragma unroll
    for (int mt = 0; mt < 2; mt++)
        #pragma unroll
        for (int nt = 0; nt < 4; nt++)
            #pragma unroll
            for (int j = 0; j < 4; j++) acc[mt][nt][j] = 0.0f;

    #pragma unroll
    for (int ks = 0; ks < 8; ks++) {
        unsigned kbyte = (unsigned)(ks * 32);
        unsigned ah[2][4], bh[4][2];
        ldsm4(ah[0], AhB + aoff[0] + kbyte);
        ldsm4(ah[1], AhB + aoff[1] + kbyte);
        #pragma unroll
        for (int p = 0; p < 2; p++) {
            unsigned th[4];
            ldsm4(th, WhB + boff[p] + kbyte);
            bh[2 * p][0] = th[0]; bh[2 * p][1] = th[1];
            bh[2 * p + 1][0] = th[2]; bh[2 * p + 1][1] = th[3];
        }
        #pragma unroll
        for (int mt = 0; mt < 2; mt++)
            #pragma unroll
            for (int nt = 0; nt < 4; nt++)
                mma_f16(acc[mt][nt], ah[mt], bh[nt]);
    }

    if (MODE == 2) {
        float* w2s = ext;
        float* s0 = ext + 256;
        float* s1 = ext + 384;
        #pragma unroll
        for (int mt = 0; mt < 2; mt++) {
            float p0a = 0.f, p1a = 0.f, p0b = 0.f, p1b = 0.f;
            #pragma unroll
            for (int nt = 0; nt < 4; nt++) {
                int col = warp_n + nt * 8 + 2 * qc;
                float b0 = bias[col], b1v = bias[col + 1];
                float v0 = fmaxf(acc[mt][nt][0] + b0, 0.f);
                float v1 = fmaxf(acc[mt][nt][1] + b1v, 0.f);
                float v2 = fmaxf(acc[mt][nt][2] + b0, 0.f);
                float v3 = fmaxf(acc[mt][nt][3] + b1v, 0.f);
                float w00 = w2s[col * 2],     w01 = w2s[col * 2 + 1];
                float w10 = w2s[col * 2 + 2], w11 = w2s[col * 2 + 3];
                p0a += v0 * w00 + v1 * w10;
                p1a += v0 * w01 + v1 * w11;
                p0b += v2 * w00 + v3 * w10;
                p1b += v2 * w01 + v3 * w11;
            }
            int ra = warp_m + mt * 16 + gr;
            atomicAdd(&s0[ra], p0a);
            atomicAdd(&s1[ra], p1a);
            atomicAdd(&s0[ra + 8], p0b);
            atomicAdd(&s1[ra + 8], p1b);
        }
        __syncthreads();
        if (tid < 128) {
            int m = m0 + tid;
            if (m < M) {
                float v0 = s0[tid] + b2[0];
                float v1 = s1[tid] + b2[1];
                float mx = fmaxf(v0, v1);
                float e0 = __expf(v0 - mx), e1 = __expf(v1 - mx);
                float inv = 1.0f / (e0 + e1);
                C[2 * m] = e0 * inv;
                C[2 * m + 1] = e1 * inv;
            }
        }
        return;
    }

    #pragma unroll
    for (int nt = 0; nt < 4; nt++) {
        int col = warp_n + nt * 8 + 2 * qc;
        float b0 = bias ? bias[col] : 0.0f;
        float b1v = bias ? bias[col + 1] : 0.0f;
        #pragma unroll
        for (int mt = 0; mt < 2; mt++) {
            int r0 = m0 + warp_m + mt * 16 + gr;
            float v0 = acc[mt][nt][0] + b0;
            float v1 = acc[mt][nt][1] + b1v;
            float v2 = acc[mt][nt][2] + b0;
            float v3 = acc[mt][nt][3] + b1v;
            if (relu) {
                v0 = fmaxf(v0, 0.0f); v1 = fmaxf(v1, 0.0f);
                v2 = fmaxf(v2, 0.0f); v3 = fmaxf(v3, 0.0f);
            }
            if (OUT16) {
                __half* C16 = (__half*)C;
                if (r0 < M)
                    *(unsigned*)(C16 + (size_t)r0 * DD + col) = pack_f16(v0, v1);
                if (r0 + 8 < M)
                    *(unsigned*)(C16 + (size_t)(r0 + 8) * DD + col) =
                        pack_f16(v2, v3);
            } else {
                if (r0 < M)
                    *(float2*)(C + (size_t)r0 * DD + col) = make_float2(v0, v1);
                if (r0 + 8 < M)
                    *(float2*)(C + (size_t)(r0 + 8) * DD + col) =
                        make_float2(v2, v3);
            }
        }
    }
}

// ---------------- GCN aggregation: fp16 gather in, fp16 out -------------------
__global__ __launch_bounds__(256)
void k_agg16(const __half* __restrict__ t,
             const float* __restrict__ bias,
             __half* __restrict__ outh) {
    int w = (blockIdx.x * blockDim.x + threadIdx.x) >> 5;
    int lane = threadIdx.x & 31;
    if (w >= NN) return;
    float di = g_dis[w];
    float sw = di * di;
    const uint2* t2 = (const uint2*)t;
    float ax, ay, az, aw_;
    {
        uint2 u = t2[(size_t)w * 32 + lane];
        float2 lo = __half22float2(*(const __half2*)&u.x);
        float2 hi = __half22float2(*(const __half2*)&u.y);
        ax = sw * lo.x; ay = sw * lo.y; az = sw * hi.x; aw_ = sw * hi.y;
    }
    int s = g_ptr[w], e = g_ptr[w + 1];
    int j = s;
    for (; j + 4 <= e; j += 4) {
        int2 e0 = g_edge[j], e1 = g_edge[j + 1];
        int2 e2 = g_edge[j + 2], e3 = g_edge[j + 3];
        uint2 u0 = t2[(size_t)e0.x * 32 + lane];
        uint2 u1 = t2[(size_t)e1.x * 32 + lane];
        uint2 u2 = t2[(size_t)e2.x * 32 + lane];
        uint2 u3 = t2[(size_t)e3.x * 32 + lane];
        float w0 = __int_as_float(e0.y), w1 = __int_as_float(e1.y);
        float w2 = __int_as_float(e2.y), w3 = __int_as_float(e3.y);
        float2 a0 = __half22float2(*(const __half2*)&u0.x);
        float2 b0 = __half22float2(*(const __half2*)&u0.y);
        float2 a1 = __half22float2(*(const __half2*)&u1.x);
        float2 b1 = __half22float2(*(const __half2*)&u1.y);
        float2 a2 = __half22float2(*(const __half2*)&u2.x);
        float2 b2 = __half22float2(*(const __half2*)&u2.y);
        float2 a3 = __half22float2(*(const __half2*)&u3.x);
        float2 b3 = __half22float2(*(const __half2*)&u3.y);
        ax += w0 * a0.x + w1 * a1.x + w2 * a2.x + w3 * a3.x;
        ay += w0 * a0.y + w1 * a1.y + w2 * a2.y + w3 * a3.y;
        az += w0 * b0.x + w1 * b1.x + w2 * b2.x + w3 * b3.x;
        aw_ += w0 * b0.y + w1 * b1.y + w2 * b2.y + w3 * b3.y;
    }
    for (; j < e; j++) {
        int2 ed = g_edge[j];
        uint2 u = t2[(size_t)ed.x * 32 + lane];
        float wt = __int_as_float(ed.y);
        float2 lo = __half22float2(*(const __half2*)&u.x);
        float2 hi = __half22float2(*(const __half2*)&u.y);
        ax += wt * lo.x; ay += wt * lo.y; az += wt * hi.x; aw_ += wt * hi.y;
    }
    float4 b = ((const float4*)bias)[lane];
    __half2 lo = __floats2half2_rn(fmaxf(ax + b.x, 0.0f),
                                   fmaxf(ay + b.y, 0.0f));
    __half2 hi = __floats2half2_rn(fmaxf(az + b.z, 0.0f),
                                   fmaxf(aw_ + b.w, 0.0f));
    uint2 o;
    o.x = *(unsigned*)&lo;
    o.y = *(unsigned*)&hi;
    ((uint2*)outh)[(size_t)w * 32 + lane] = o;
}

// ---------------- launch -------------------------------------------------------
extern "C" void kernel_launch(void* const* d_in, const int* in_sizes, int n_in,
                              void* d_out, int out_size) {
    const float* x      = (const float*)d_in[0];
    const void*  ei     = d_in[1];
    const float* ew     = (const float*)d_in[2];
    const float* enc_W1 = (const float*)d_in[3];
    const float* enc_b1 = (const float*)d_in[4];
    const float* enc_W2 = (const float*)d_in[5];
    const float* enc_b2 = (const float*)d_in[6];
    const float* c1_W   = (const float*)d_in[7];
    const float* c1_b   = (const float*)d_in[8];
    const float* c2_W   = (const float*)d_in[9];
    const float* c2_b   = (const float*)d_in[10];
    const float* dec_W1 = (const float*)d_in[11];
    const float* dec_b1 = (const float*)d_in[12];
    const float* dec_W2 = (const float*)d_in[13];
    const float* dec_b2 = (const float*)d_in[14];
    float* out = (float*)d_out;

    void *pA, *pB, *pC, *pWt, *pBc;
    cudaGetSymbolAddress(&pA, g_bufA);
    cudaGetSymbolAddress(&pB, g_bufB);
    cudaGetSymbolAddress(&pC, g_bufC);
    cudaGetSymbolAddress(&pWt, g_Wt);
    cudaGetSymbolAddress(&pBc, g_bcomb);
    const __half* Wt = (const __half*)pWt;
    const float* bcomb = (const float*)pBc;

    static cudaStream_t s2 = nullptr;
    static cudaEvent_t evDet = nullptr, evPrep = nullptr;
    if (s2 == nullptr) {
        cudaStreamCreateWithFlags(&s2, cudaStreamNonBlocking);
        cudaEventCreateWithFlags(&evDet, cudaEventDisableTiming);
        cudaEventCreateWithFlags(&evPrep, cudaEventDisableTiming);
    }

    const int mma_smem =
        2 * 128 * PITCH * (int)sizeof(__half) + EXT_FLOATS * 4; // 86528
    cudaFuncSetAttribute(k_gemm<0, 1>,
                         cudaFuncAttributeMaxDynamicSharedMemorySize, mma_smem);
    cudaFuncSetAttribute(k_gemm<1, 1>,
                         cudaFuncAttributeMaxDynamicSharedMemorySize, mma_smem);
    cudaFuncSetAttribute(k_gemm<2, 0>,
                         cudaFuncAttributeMaxDynamicSharedMemorySize, mma_smem);

    int nScanBlocks = (NN + 1023) / 1024;
    int gemm_grid = (NN + 127) / 128;
    int agg_grid = (NN * 32 + 255) / 256;

    // ---- legal capture fork: s2 joins via event BEFORE any s2 launch --------
    k_detect<<<1, 32>>>((const unsigned int*)ei);        // stream 0 (capture origin)
    cudaEventRecord(evDet, 0);
    cudaStreamWaitEvent(s2, evDet, 0);                   // s2 joins the capture

    k_zero_node<<<(NN + 255) / 256, 256, 0, s2>>>();
    k_hist<<<(NE + 255) / 256, 256, 0, s2>>>(ei, ew);
    k_scan1<<<nScanBlocks, 1024, 0, s2>>>();
    k_scan2<<<1, 128, 0, s2>>>(nScanBlocks);
    k_scan3<<<(NN + 255) / 256, 256, 0, s2>>>();
    k_fill<<<(NE + 255) / 256, 256, 0, s2>>>(ei, ew);
    cudaEventRecord(evPrep, s2);

    // ---- main chain: combine -> fused encoder+conv1 GEMM --------------------
    k_combine<<<128, 512>>>(enc_W2, c1_W, enc_b2);
    k_gemm<1, 1><<<gemm_grid, 512, mma_smem>>>(nullptr, Wt,
                                               bcomb, (float*)pA, NN, 0,
                                               x, enc_W1, enc_b1,
                                               nullptr, nullptr);
    k_splitW<<<128, 256>>>(c2_W, dec_W1);   // needed only by gemm2/gemm3

    // ---- join: aggregation needs CSR + t1 -----------------------------------
    cudaStreamWaitEvent(0, evPrep, 0);
    k_agg16<<<agg_grid, 256>>>((const __half*)pA, c1_b, (__half*)pC);
    // conv2 GEMM: fp16 in (agg1 out), fp16 t2 out in A
    k_gemm<0, 1><<<gemm_grid, 512, mma_smem>>>((const __half*)pC,
                                               Wt + 16384,
                                               nullptr, (float*)pA, NN, 0,
                                               nullptr, nullptr, nullptr,
                                               nullptr, nullptr);
    k_agg16<<<agg_grid, 256>>>((const __half*)pA, c2_b, (__half*)pB);
    // decoder (fused): fp16 in (agg2 out)
    k_gemm<2, 0><<<gemm_grid, 512, mma_smem>>>((const __half*)pB,
                                               Wt + 2 * 16384,
                                               dec_b1, out, NN, 1,
                                               nullptr, nullptr, nullptr,
                                               dec_W2, dec_b2);
}